// round 2
// baseline (speedup 1.0000x reference)
#include <cuda_runtime.h>

#define TPB   512
#define CAP   4096
#define NB    2048
#define TOPN  2048
#define EPSF  1e-9f

__device__ __forceinline__ float key_p(unsigned long long k) {
    return __uint_as_float((unsigned int)(k >> 32));
}

// Pinned-arithmetic p computation: MUST be bitwise identical in every pass.
__device__ __forceinline__ unsigned int pbits_of(float l, float temp, float m, float Z) {
    float y = __fdiv_rn(l, temp);
    float d = __fsub_rn(y, m);
    float e = expf(d);
    float p = __fdiv_rn(e, Z);
    return __float_as_uint(p);
}

__global__ __launch_bounds__(TPB, 2)
void sampler_kernel(const float* __restrict__ logits,
                    const float* __restrict__ temps,
                    const int*   __restrict__ topks,
                    const float* __restrict__ topps,
                    const float* __restrict__ minps,
                    const int*   __restrict__ poss,
                    const int*   __restrict__ seeds,
                    float* __restrict__ out_ids,
                    float* __restrict__ out_lp,
                    int V, int write_lp)
{
    __shared__ unsigned long long cand[CAP];   // 32 KB
    __shared__ unsigned int hist[NB];          // 8 KB
    __shared__ float redF[TPB];                // 2 KB
    __shared__ float redS[TPB];                // 2 KB
    __shared__ int   redI[TPB];                // 2 KB
    __shared__ float sh_m, sh_Z, sh_logZ;
    __shared__ unsigned int sh_thresh, sh_cnt, sh_above;
    __shared__ int sh_b, sh_refine, sh_Kcut, sh_jwin, sh_token;

    const int row = blockIdx.x;
    const int tid = threadIdx.x;
    const float temp = temps[row];
    const float* lrow = logits + (size_t)row * V;
    float* lprow = out_lp + (size_t)row * V;

    // ---------- Pass A: online max + sum of exp ----------
    float m = -3.402823466e38f;
    float s = 0.0f;
    for (int j = tid * 4; j < V; j += TPB * 4) {
        float4 v = *reinterpret_cast<const float4*>(lrow + j);
        float ys[4];
        ys[0] = __fdiv_rn(v.x, temp); ys[1] = __fdiv_rn(v.y, temp);
        ys[2] = __fdiv_rn(v.z, temp); ys[3] = __fdiv_rn(v.w, temp);
        #pragma unroll
        for (int q = 0; q < 4; q++) {
            float y = ys[q];
            if (y > m) { s *= expf(m - y); m = y; }
            s += expf(y - m);
        }
    }
    redF[tid] = m; redS[tid] = s;
    __syncthreads();
    for (int off = TPB / 2; off > 0; off >>= 1) {
        if (tid < off) {
            float m2 = redF[tid + off], s2 = redS[tid + off];
            float M = fmaxf(redF[tid], m2);
            redS[tid] = redS[tid] * expf(redF[tid] - M) + s2 * expf(m2 - M);
            redF[tid] = M;
        }
        __syncthreads();
    }
    if (tid == 0) { sh_m = redF[0]; sh_Z = redS[0]; sh_logZ = logf(redS[0]); }
    __syncthreads();
    m = sh_m;
    const float Z = sh_Z;
    const float logZ = sh_logZ;

    // ---------- Pass B: logprobs out + p-bits histogram ----------
    for (int i = tid; i < NB; i += TPB) hist[i] = 0;
    __syncthreads();
    for (int j = tid * 4; j < V; j += TPB * 4) {
        float4 v = *reinterpret_cast<const float4*>(lrow + j);
        float4 o;
        {
            float y = __fdiv_rn(v.x, temp); float d = __fsub_rn(y, m);
            atomicAdd(&hist[__float_as_uint(__fdiv_rn(expf(d), Z)) >> 20], 1u);
            o.x = d - logZ;
        }
        {
            float y = __fdiv_rn(v.y, temp); float d = __fsub_rn(y, m);
            atomicAdd(&hist[__float_as_uint(__fdiv_rn(expf(d), Z)) >> 20], 1u);
            o.y = d - logZ;
        }
        {
            float y = __fdiv_rn(v.z, temp); float d = __fsub_rn(y, m);
            atomicAdd(&hist[__float_as_uint(__fdiv_rn(expf(d), Z)) >> 20], 1u);
            o.z = d - logZ;
        }
        {
            float y = __fdiv_rn(v.w, temp); float d = __fsub_rn(y, m);
            atomicAdd(&hist[__float_as_uint(__fdiv_rn(expf(d), Z)) >> 20], 1u);
            o.w = d - logZ;
        }
        if (write_lp) *reinterpret_cast<float4*>(lprow + j) = o;
    }
    __syncthreads();

    // ---------- threshold bucket for top-TOPN ----------
    if (tid == 0) {
        unsigned cum = 0; int b = NB - 1;
        for (; b >= 0; --b) {
            unsigned c = hist[b];
            if (cum + c >= TOPN) break;
            cum += c;
        }
        if (b < 0) b = 0;
        sh_b = b; sh_above = cum;
        unsigned tot = cum + hist[b];
        sh_refine = (tot > CAP) ? 1 : 0;
        if (tot <= CAP) sh_thresh = ((unsigned)b) << 20;
    }
    __syncthreads();
    if (sh_refine) {
        for (int i = tid; i < NB; i += TPB) hist[i] = 0;
        __syncthreads();
        int b = sh_b;
        for (int j = tid * 4; j < V; j += TPB * 4) {
            float4 v = *reinterpret_cast<const float4*>(lrow + j);
            float ls[4] = {v.x, v.y, v.z, v.w};
            #pragma unroll
            for (int q = 0; q < 4; q++) {
                unsigned bits = pbits_of(ls[q], temp, m, Z);
                if ((int)(bits >> 20) == b) atomicAdd(&hist[(bits >> 9) & (NB - 1)], 1u);
            }
        }
        __syncthreads();
        if (tid == 0) {
            unsigned cum = sh_above; int sb = NB - 1;
            for (; sb >= 0; --sb) {
                unsigned c = hist[sb];
                if (cum + c >= TOPN) break;
                cum += c;
            }
            if (sb < 0) sb = 0;
            sh_thresh = (((unsigned)sh_b) << 20) | (((unsigned)sb) << 9);
        }
        __syncthreads();
    }

    // ---------- gather candidates ----------
    if (tid == 0) sh_cnt = 0;
    __syncthreads();
    {
        unsigned th = sh_thresh;
        for (int j = tid * 4; j < V; j += TPB * 4) {
            float4 v = *reinterpret_cast<const float4*>(lrow + j);
            float ls[4] = {v.x, v.y, v.z, v.w};
            #pragma unroll
            for (int q = 0; q < 4; q++) {
                unsigned bits = pbits_of(ls[q], temp, m, Z);
                if (bits >= th) {
                    unsigned pos = atomicAdd(&sh_cnt, 1u);
                    if (pos < CAP)
                        cand[pos] = ((unsigned long long)bits << 32) | (unsigned)(j + q);
                }
            }
        }
    }
    __syncthreads();
    {
        int n = (int)min(sh_cnt, (unsigned)CAP);
        for (int i = tid; i < CAP; i += TPB)
            if (i >= n) cand[i] = 0ULL;
    }
    __syncthreads();

    // ---------- bitonic sort (descending by 64-bit key) ----------
    for (int k = 2; k <= CAP; k <<= 1) {
        for (int jj = k >> 1; jj > 0; jj >>= 1) {
            for (int i = tid; i < CAP; i += TPB) {
                int l = i ^ jj;
                if (l > i) {
                    unsigned long long a = cand[i], b2 = cand[l];
                    bool descBlock = ((i & k) == 0);
                    bool doswap = descBlock ? (a < b2) : (a > b2);
                    if (doswap) { cand[i] = b2; cand[l] = a; }
                }
            }
            __syncthreads();
        }
    }

    // ---------- inclusive scan over top-TOPN probs ----------
    float* src = (float*)hist;                 // 2048 floats
    float* dst = (float*)(cand + TOPN);        // reuse upper cand space
    for (int i = tid; i < TOPN; i += TPB) src[i] = key_p(cand[i]);
    __syncthreads();
    for (int off = 1; off < TOPN; off <<= 1) {
        for (int i = tid; i < TOPN; i += TPB) {
            float x = src[i];
            if (i >= off) x += src[i - off];
            dst[i] = x;
        }
        __syncthreads();
        float* t = src; src = dst; dst = t;
    }

    // ---------- K_cut: first violated position ----------
    {
        int tk = topks[row]; if (tk > TOPN) tk = TOPN;
        float tp = topps[row];
        float mp = minps[row];
        float p0 = key_p(cand[0]);
        float thr = p0 * mp;
        int kl = tk;
        for (int i = tid; i < tk; i += TPB) {
            float pi = key_p(cand[i]);
            if ((src[i] - pi) > tp || pi < thr) kl = min(kl, i);
        }
        redI[tid] = kl;
        __syncthreads();
        for (int off = TPB / 2; off > 0; off >>= 1) {
            if (tid < off) redI[tid] = min(redI[tid], redI[tid + off]);
            __syncthreads();
        }
        if (tid == 0) sh_Kcut = redI[0];
        __syncthreads();
    }
    const int Kcut = sh_Kcut;

    // ---------- full-row gumbel argmax ----------
    {
        unsigned ss = (unsigned)seeds[row] * 19349663u ^ (unsigned)poss[row] * 73856093u;
        const float CZ = logf(EPSF);
        float bv = -3.402823466e38f; int bj = V;
        for (int j = tid; j < V; j += TPB) {
            unsigned h = ss * 805306457u ^ (unsigned)j * 479001599u;
            float u = (float)(h & 0xFFFFFFu) * (1.0f / 16777216.0f);
            float g = -logf(-logf(u + EPSF) + EPSF);
            float base = (j < Kcut) ? logf(key_p(cand[j]) + EPSF) : CZ;
            float val = base + g;
            if (val > bv) { bv = val; bj = j; }
        }
        redF[tid] = bv; redI[tid] = bj;
        __syncthreads();
        for (int off = TPB / 2; off > 0; off >>= 1) {
            if (tid < off) {
                float v2 = redF[tid + off]; int j2 = redI[tid + off];
                if (v2 > redF[tid] || (v2 == redF[tid] && j2 < redI[tid])) {
                    redF[tid] = v2; redI[tid] = j2;
                }
            }
            __syncthreads();
        }
        if (tid == 0) {
            int jw = redI[0];
            sh_jwin = jw;
            sh_token = (jw < TOPN) ? (int)(unsigned)(cand[jw] & 0xFFFFFFFFULL) : -1;
        }
        __syncthreads();
    }

    // ---------- rare exact fallback: winner rank >= TOPN ----------
    if (sh_token < 0) {
        int jw = sh_jwin;
        auto blockCountGE = [&](unsigned t) -> int {
            int c = 0;
            for (int j = tid * 4; j < V; j += TPB * 4) {
                float4 v = *reinterpret_cast<const float4*>(lrow + j);
                float ls[4] = {v.x, v.y, v.z, v.w};
                #pragma unroll
                for (int q = 0; q < 4; q++)
                    c += (pbits_of(ls[q], temp, m, Z) >= t) ? 1 : 0;
            }
            redI[tid] = c; __syncthreads();
            for (int off = TPB / 2; off > 0; off >>= 1) {
                if (tid < off) redI[tid] += redI[tid + off];
                __syncthreads();
            }
            int tot = redI[0]; __syncthreads();
            return tot;
        };
        // binary search: largest P with count_ge(P) >= jw+1  → P = p_bits at rank jw
        unsigned lo = 0, hi = 0x7F800000u;
        while (lo < hi) {
            unsigned mid = lo + (hi - lo + 1u) / 2u;
            if (blockCountGE(mid) >= jw + 1) lo = mid; else hi = mid - 1u;
        }
        unsigned P = lo;
        int cgt = blockCountGE(P + 1u);
        int r = jw - cgt;   // rank among equal-p elements (idx descending)
        auto blockCountEqGe = [&](unsigned Pv, int vidx) -> int {
            int c = 0;
            for (int j = tid * 4; j < V; j += TPB * 4) {
                float4 v = *reinterpret_cast<const float4*>(lrow + j);
                float ls[4] = {v.x, v.y, v.z, v.w};
                #pragma unroll
                for (int q = 0; q < 4; q++)
                    c += (pbits_of(ls[q], temp, m, Z) == Pv && (j + q) >= vidx) ? 1 : 0;
            }
            redI[tid] = c; __syncthreads();
            for (int off = TPB / 2; off > 0; off >>= 1) {
                if (tid < off) redI[tid] += redI[tid + off];
                __syncthreads();
            }
            int tot = redI[0]; __syncthreads();
            return tot;
        };
        // (r+1)-th largest idx among {i : bits == P}
        int l2 = 0, h2 = V - 1;
        while (l2 < h2) {
            int midv = l2 + (h2 - l2 + 1) / 2;
            if (blockCountEqGe(P, midv) >= r + 1) l2 = midv; else h2 = midv - 1;
        }
        if (tid == 0) sh_token = l2;
        __syncthreads();
    }

    if (tid == 0 && out_ids) out_ids[row] = (float)sh_token;
}

extern "C" void kernel_launch(void* const* d_in, const int* in_sizes, int n_in,
                              void* d_out, int out_size) {
    const float* logits = (const float*)d_in[0];
    const float* temps  = (const float*)d_in[1];
    const int*   topks  = (const int*)d_in[2];
    const float* topps  = (const float*)d_in[3];
    const float* minps  = (const float*)d_in[4];
    const int*   poss   = (const int*)d_in[5];
    const int*   seeds  = (const int*)d_in[6];

    int B = in_sizes[1];              // temperatures: [B,1]
    int V = in_sizes[0] / B;          // logits: [B,V]
    long long BV = (long long)B * (long long)V;

    float* out = (float*)d_out;
    float* out_ids = nullptr;
    float* out_lp = nullptr;
    int write_lp = 0;

    if ((long long)out_size >= BV + B) {           // [ids(B), logprobs(B*V)]
        out_ids = out; out_lp = out + B; write_lp = 1;
    } else if ((long long)out_size >= BV) {        // logprobs only
        out_lp = out; write_lp = 1;
    } else {                                        // ids only
        out_ids = out; out_lp = out; write_lp = 0;
    }

    sampler_kernel<<<B, TPB>>>(logits, temps, topks, topps, minps, poss, seeds,
                               out_ids, out_lp, V, write_lp);
}